// round 7
// baseline (speedup 1.0000x reference)
#include <cuda_runtime.h>
#include <math.h>

// ChamferLoss: bs=4, npts=4096, dim=3.
// dist^2(q,r) = ||q||^2 + (||r||^2 - 2 q.r); minimize squared dist, sqrt once.
// Register-blocked: each thread holds Q=4 queries; each loaded ref group (4 refs,
// packed f32x2) feeds 4 queries -> 24 fma2 per 64B of LDS.
// TPB=512 (4 warps/SMSP) + RS=8 reference splits -> 128 blocks, one balanced wave,
// fma-pipe-bound. Distributed epilogue via self-resetting counters (single kernel,
// graph-replayable, deterministic summation order).

#define NPTS 4096
#define BS   4
#define TPB  512
#define Q    4                       // queries per thread
#define RS   8                       // reference splits
#define RPB  (NPTS / RS)             // 512 refs per block
#define QPB  (TPB * Q)               // 2048 queries per block
#define NQT  (NPTS / QPB)            // 2 query tiles
#define NGRP (NQT * BS * 2)          // 16 query-tile groups
#define NBLK (NGRP * RS)             // 128 blocks == one balanced wave
#define NWARP (TPB / 32)             // 16

__device__ float g_pmin[2 * BS * NPTS * RS];   // [dir][b][q][rs]
__device__ float g_gsum[NGRP];
__device__ unsigned int g_gc[NGRP];            // zero-init, self-resetting
__device__ unsigned int g_fc;                  // zero-init, self-resetting

__device__ __forceinline__ unsigned long long bcast2(float f) {
    unsigned long long v;
    asm("mov.b64 %0, {%1, %1};" : "=l"(v) : "r"(__float_as_uint(f)));
    return v;
}
__device__ __forceinline__ void unpack2(unsigned long long v, float& a, float& b) {
    unsigned lo, hi;
    asm("mov.b64 {%0, %1}, %2;" : "=r"(lo), "=r"(hi) : "l"(v));
    a = __uint_as_float(lo); b = __uint_as_float(hi);
}

__global__ __launch_bounds__(TPB, 1) void chamfer_main(
    const float* __restrict__ x, const float* __restrict__ y, float* __restrict__ out)
{
    __shared__ float s[RPB * 4];          // 8 KB
    __shared__ float red[NWARP];
    __shared__ int   s_last;

    const int tid = threadIdx.x;
    const int qt  = blockIdx.x;           // 0..NQT-1
    const int b   = blockIdx.y;           // 0..BS-1
    const int z   = blockIdx.z;           // 0..2*RS-1
    const int dir = z >> 3;               // z / RS
    const int rs  = z & 7;                // z % RS

    const float* __restrict__ q  = dir ? y : x;
    const float* __restrict__ r  = dir ? x : y;
    const float* __restrict__ rb = r + ((size_t)b * NPTS + (size_t)rs * RPB) * 3;

    // Stage this block's reference slice: -2r (SoA groups of 4) and ||r||^2.
    {
        int i = tid;                      // RPB == TPB
        if (i < RPB) {
            float rx = rb[3 * i + 0];
            float ry = rb[3 * i + 1];
            float rz = rb[3 * i + 2];
            float* base = s + ((i >> 2) << 4) + (i & 3);
            base[0]  = -2.0f * rx;
            base[4]  = -2.0f * ry;
            base[8]  = -2.0f * rz;
            base[12] = fmaf(rx, rx, fmaf(ry, ry, rz * rz));
        }
    }

    // Q=4 query points per thread (coalesced loads within each k).
    const int qbase = qt * QPB + tid;
    unsigned long long bx[Q], by[Q], bz[Q];
    float qsq[Q];
    #pragma unroll
    for (int k = 0; k < Q; ++k) {
        const float* qp = q + ((size_t)b * NPTS + (qbase + k * TPB)) * 3;
        float qx = qp[0], qy = qp[1], qz = qp[2];
        qsq[k] = fmaf(qx, qx, fmaf(qy, qy, qz * qz));
        bx[k] = bcast2(qx); by[k] = bcast2(qy); bz[k] = bcast2(qz);
    }

    __syncthreads();

    unsigned sa = (unsigned)__cvta_generic_to_shared(s);
    float mac[Q][4];
    #pragma unroll
    for (int k = 0; k < Q; ++k) {
        mac[k][0] = 3.402823466e+38f; mac[k][1] = 3.402823466e+38f;
        mac[k][2] = 3.402823466e+38f; mac[k][3] = 3.402823466e+38f;
    }

    #pragma unroll 4
    for (int g = 0; g < RPB / 4; ++g, sa += 64) {
        unsigned long long X01, X23, Y01, Y23, Z01, Z23, H01, H23;
        asm("ld.shared.v2.u64 {%0,%1}, [%2];"    : "=l"(X01), "=l"(X23) : "r"(sa));
        asm("ld.shared.v2.u64 {%0,%1}, [%2+16];" : "=l"(Y01), "=l"(Y23) : "r"(sa));
        asm("ld.shared.v2.u64 {%0,%1}, [%2+32];" : "=l"(Z01), "=l"(Z23) : "r"(sa));
        asm("ld.shared.v2.u64 {%0,%1}, [%2+48];" : "=l"(H01), "=l"(H23) : "r"(sa));

        #pragma unroll
        for (int k = 0; k < Q; ++k) {
            unsigned long long t0, t1;
            asm("fma.rn.f32x2 %0, %1, %2, %3;" : "=l"(t0) : "l"(bz[k]), "l"(Z01), "l"(H01));
            asm("fma.rn.f32x2 %0, %1, %2, %0;" : "+l"(t0) : "l"(by[k]), "l"(Y01));
            asm("fma.rn.f32x2 %0, %1, %2, %0;" : "+l"(t0) : "l"(bx[k]), "l"(X01));
            asm("fma.rn.f32x2 %0, %1, %2, %3;" : "=l"(t1) : "l"(bz[k]), "l"(Z23), "l"(H23));
            asm("fma.rn.f32x2 %0, %1, %2, %0;" : "+l"(t1) : "l"(by[k]), "l"(Y23));
            asm("fma.rn.f32x2 %0, %1, %2, %0;" : "+l"(t1) : "l"(bx[k]), "l"(X23));
            float a0, a1, a2, a3;
            unpack2(t0, a0, a1);
            unpack2(t1, a2, a3);
            mac[k][0] = fminf(mac[k][0], a0);
            mac[k][1] = fminf(mac[k][1], a1);
            mac[k][2] = fminf(mac[k][2], a2);
            mac[k][3] = fminf(mac[k][3], a3);
        }
    }

    // Write per-query partial (qsq + min over this ref slice).
    const size_t obase = (size_t)(dir * BS + b) * NPTS;
    #pragma unroll
    for (int k = 0; k < Q; ++k) {
        float m = fminf(fminf(mac[k][0], mac[k][1]), fminf(mac[k][2], mac[k][3]));
        g_pmin[(obase + (qbase + k * TPB)) * RS + rs] = qsq[k] + m;
    }

    // ---- Distributed epilogue: last RS-block of each group combines. ----
    const int gidx = (dir * BS + b) * NQT + qt;
    __threadfence();
    if (tid == 0)
        s_last = (atomicAdd(&g_gc[gidx], 1u) == RS - 1) ? 1 : 0;
    __syncthreads();

    if (s_last) {
        if (tid == 0) g_gc[gidx] = 0;     // self-reset for graph replay
        const float4* pm = (const float4*)g_pmin;   // RS=8 -> 2 float4 per query
        float v = 0.0f;
        #pragma unroll
        for (int k = 0; k < Q; ++k) {
            size_t qi = obase + (qbase + k * TPB);
            float4 p0 = __ldcg(pm + 2 * qi + 0);
            float4 p1 = __ldcg(pm + 2 * qi + 1);
            float m = fminf(fminf(fminf(p0.x, p0.y), fminf(p0.z, p0.w)),
                            fminf(fminf(p1.x, p1.y), fminf(p1.z, p1.w)));
            v += sqrtf(1e-6f + m);
        }
        #pragma unroll
        for (int off = 16; off; off >>= 1)
            v += __shfl_down_sync(0xFFFFFFFFu, v, off);
        if ((tid & 31) == 0) red[tid >> 5] = v;
        __syncthreads();
        if (tid == 0) {
            float t = 0.0f;
            #pragma unroll
            for (int i = 0; i < NWARP; ++i) t += red[i];
            g_gsum[gidx] = t;
            __threadfence();
            if (atomicAdd(&g_fc, 1u) == NGRP - 1) {
                float tot = 0.0f;
                volatile float* gs = g_gsum;
                #pragma unroll
                for (int i = 0; i < NGRP; ++i) tot += gs[i];
                out[0] = tot * (1.0f / 16384.0f);   // (S1 + S2) / (BS * NPTS)
                g_fc = 0;                            // self-reset for graph replay
            }
        }
    }
}

extern "C" void kernel_launch(void* const* d_in, const int* in_sizes, int n_in,
                              void* d_out, int out_size)
{
    const float* x = (const float*)d_in[0];
    const float* y = (const float*)d_in[1];
    float* out = (float*)d_out;

    chamfer_main<<<dim3(NQT, BS, 2 * RS), TPB>>>(x, y, out);
}